// round 8
// baseline (speedup 1.0000x reference)
#include <cuda_runtime.h>
#include <cstdint>

#define TOKENS 65536
#define KCODES 1024
#define DDIM   64
#define HW     4096
#define TM     128
#define TN     128
#define NCH    (KCODES / TN)

// smem: sidx[128] | fragment-ordered B arrays (A raw staging overlaps B region)
#define SM_IDX  0
#define SM_B    512
#define BHI_U32 (9 * 16 * 64)              // 9 ksteps (8 data + 1 norm)
#define BLO_U32 (8 * 16 * 64)
#define SMEM_TOTAL (SM_B + (BHI_U32 + BLO_U32) * 4)   // 70144 B

typedef unsigned long long u64;

__device__ float g_hn[KCODES];

__global__ void vq_norms(const float* __restrict__ cb) {
    int w = (blockIdx.x * blockDim.x + threadIdx.x) >> 5;
    int lane = threadIdx.x & 31;
    if (w < KCODES) {
        float v0 = cb[w * DDIM + lane];
        float v1 = cb[w * DDIM + 32 + lane];
        float s = v0 * v0 + v1 * v1;
        #pragma unroll
        for (int m = 16; m >= 1; m >>= 1) s += __shfl_xor_sync(0xffffffffu, s, m);
        if (lane == 0) g_hn[w] = 0.5f * s;
    }
}

__device__ __forceinline__ uint32_t f2tf32(float v) {
    uint32_t r; asm("cvt.rna.tf32.f32 %0, %1;" : "=r"(r) : "f"(v)); return r;
}

#define MMA(d, a0, a1, a2, a3, b0, b1)                                        \
    asm("mma.sync.aligned.m16n8k8.row.col.f32.tf32.tf32.f32 "                 \
        "{%0,%1,%2,%3}, {%4,%5,%6,%7}, {%8,%9}, {%0,%1,%2,%3};"               \
        : "+f"((d)[0]), "+f"((d)[1]), "+f"((d)[2]), "+f"((d)[3])              \
        : "r"(a0), "r"(a1), "r"(a2), "r"(a3), "r"(b0), "r"(b1))

// argmax(x.c - 0.5|c|^2) via split-tf32 mma.sync (3 passes + folded norm kstep).
// 128 tokens/CTA, 8 warps x 16 tokens; per chunk 128 codes = 16 ntiles.
__global__ __launch_bounds__(256, 1)
void vq_tc(const float* __restrict__ inp, const float* __restrict__ cb,
           float* __restrict__ out, int out_size) {
    extern __shared__ char smem[];
    int*      sidx = (int*)(smem + SM_IDX);
    float*    araw = (float*)(smem + SM_B);          // [128][65], transient
    uint32_t* bhi  = (uint32_t*)(smem + SM_B);
    uint32_t* blo  = bhi + BHI_U32;

    int tid = threadIdx.x, wid = tid >> 5, lane = tid & 31;
    int gid = lane >> 2, tig = lane & 3;
    int n0 = blockIdx.x * TM;
    int b = n0 >> 12, s0 = n0 & (HW - 1);
    const float* ibase = inp + (long long)b * DDIM * HW + s0;

    // Stage A raw (coalesced over t), then extract per-warp tf32 hi/lo fragments.
    for (int e = tid; e < TM * DDIM; e += 256) {
        int t = e & 127, d = e >> 7;
        araw[t * 65 + d] = ibase[d * HW + t];
    }
    __syncthreads();

    int r0 = wid * 16 + gid, r1 = r0 + 8;
    uint32_t ahi[8][4], alo[8][4];
    #pragma unroll
    for (int s = 0; s < 8; ++s) {
        float v[4] = { araw[r0 * 65 + s * 8 + tig],     araw[r1 * 65 + s * 8 + tig],
                       araw[r0 * 65 + s * 8 + tig + 4], araw[r1 * 65 + s * 8 + tig + 4] };
        #pragma unroll
        for (int i = 0; i < 4; ++i) {
            ahi[s][i] = f2tf32(v[i]);
            alo[s][i] = f2tf32(v[i] - __uint_as_float(ahi[s][i]));
        }
    }
    uint32_t an = (tig < 2) ? 0x3f800000u : 0u;      // A cols 64,65 = 1.0
    __syncthreads();                                  // araw dead; B may overwrite

    float best0 = -3.4e38f, best1 = -3.4e38f;
    int bi0 = 0, bi1 = 0;

    for (int ch = 0; ch < NCH; ++ch) {
        int c0 = ch * TN;
        __syncthreads();                              // prior chunk's mma done (warp-sync)

        // B fragments, fragment-ordered: slot = ((s*16+j)*32 + lane)*2 + half
        for (int e = tid; e < TN * DDIM; e += 256) {
            int n = e >> 6, k = e & 63;
            float v = cb[(c0 + n) * DDIM + k];
            uint32_t hi = f2tf32(v);
            uint32_t lo = f2tf32(v - __uint_as_float(hi));
            int slot = ((((k >> 3) * 16 + (n >> 3)) * 32) + ((n & 7) * 4 + (k & 3))) * 2
                     + ((k >> 2) & 1);
            bhi[slot] = hi; blo[slot] = lo;
        }
        // Norm kstep (s=8): B[64][n] = -hn_hi, B[65][n] = -hn_lo, rest 0.
        for (int e = tid; e < 1024; e += 256) {
            int j = e >> 6, ln = (e >> 1) & 31, half = e & 1;
            int tg = ln & 3, n = (j << 3) | (ln >> 2);
            uint32_t val = 0;
            if (half == 0 && tg < 2) {
                float hn = -g_hn[c0 + n];
                uint32_t hh = f2tf32(hn);
                val = (tg == 0) ? hh : f2tf32(hn - __uint_as_float(hh));
            }
            bhi[(((8 * 16 + j) * 32) + ln) * 2 + half] = val;
        }
        __syncthreads();

        float acc[16][4];
        #pragma unroll
        for (int j = 0; j < 16; ++j)
            #pragma unroll
            for (int i = 0; i < 4; ++i) acc[j][i] = 0.f;

        #pragma unroll
        for (int s = 0; s < 8; ++s)
            #pragma unroll
            for (int j = 0; j < 16; ++j) {
                uint2 bh = *(const uint2*)(bhi + ((s * 16 + j) * 32 + lane) * 2);
                uint2 bl = *(const uint2*)(blo + ((s * 16 + j) * 32 + lane) * 2);
                MMA(acc[j], ahi[s][0], ahi[s][1], ahi[s][2], ahi[s][3], bh.x, bh.y);
                MMA(acc[j], ahi[s][0], ahi[s][1], ahi[s][2], ahi[s][3], bl.x, bl.y);
                MMA(acc[j], alo[s][0], alo[s][1], alo[s][2], alo[s][3], bh.x, bh.y);
            }
        #pragma unroll
        for (int j = 0; j < 16; ++j) {
            uint2 bn = *(const uint2*)(bhi + ((8 * 16 + j) * 32 + lane) * 2);
            MMA(acc[j], an, an, 0u, 0u, bn.x, bn.y);
        }

        // Running argmax on acc: cols ascend with j and within (v0,v1) -> strict >
        #pragma unroll
        for (int j = 0; j < 16; ++j) {
            int colb = c0 + j * 8 + tig * 2;
            if (acc[j][0] > best0) { best0 = acc[j][0]; bi0 = colb; }
            if (acc[j][1] > best0) { best0 = acc[j][1]; bi0 = colb + 1; }
            if (acc[j][2] > best1) { best1 = acc[j][2]; bi1 = colb; }
            if (acc[j][3] > best1) { best1 = acc[j][3]; bi1 = colb + 1; }
        }
    }

    // Reduce across the quad (lanes differing in tig hold different columns).
    #pragma unroll
    for (int m = 1; m <= 2; m <<= 1) {
        float ov; int oi;
        ov = __shfl_xor_sync(0xffffffffu, best0, m);
        oi = __shfl_xor_sync(0xffffffffu, bi0, m);
        if (ov > best0 || (ov == best0 && oi < bi0)) { best0 = ov; bi0 = oi; }
        ov = __shfl_xor_sync(0xffffffffu, best1, m);
        oi = __shfl_xor_sync(0xffffffffu, bi1, m);
        if (ov > best1 || (ov == best1 && oi < bi1)) { best1 = ov; bi1 = oi; }
    }
    if (tig == 0) { sidx[r0] = bi0; sidx[r1] = bi1; }
    __syncthreads();

    // Fused gather: out[b][d][s0+t] = cb[idx[t]][d]; coalesced writes, L2-hot reads.
    for (int e = tid; e < TM * DDIM; e += 256) {
        int d = e >> 7, t = e & 127;
        out[((long long)b * DDIM + d) * HW + s0 + t] = cb[sidx[t] * DDIM + d];
    }
    if (out_size > TOKENS * DDIM && tid < TM)
        out[TOKENS * DDIM + n0 + tid] = (float)sidx[tid];
}

extern "C" void kernel_launch(void* const* d_in, const int* in_sizes, int n_in,
                              void* d_out, int out_size) {
    const float* inp = (const float*)d_in[0];   // (16, 64, 64, 64) f32
    const float* cb  = (const float*)d_in[1];   // (1024, 64) f32
    float* out = (float*)d_out;

    cudaFuncSetAttribute(vq_tc, cudaFuncAttributeMaxDynamicSharedMemorySize, SMEM_TOTAL);

    vq_norms<<<KCODES * 32 / 256, 256>>>(cb);
    vq_tc<<<TOKENS / TM, 256, SMEM_TOTAL>>>(inp, cb, out, out_size);
}

// round 10
// speedup vs baseline: 1.4516x; 1.4516x over previous
#include <cuda_runtime.h>
#include <cstdint>

#define TOKENS 65536
#define KCODES 1024
#define DDIM   64
#define HW     4096
#define TM     128
#define TN     128
#define NCH    (KCODES / TN)

#define BHI_U32 (9 * 16 * 64)     // per chunk: 9 ksteps (8 data + 1 norm)
#define BLO_U32 (8 * 16 * 64)

#define SM_IDX 0
#define SM_A   512
#define SMEM_TOTAL (SM_A + TM * 65 * 4)

__device__ float    g_hn[KCODES];
__device__ uint32_t g_bhi[NCH * BHI_U32];   // fragment-ordered, precomputed once
__device__ uint32_t g_blo[NCH * BLO_U32];

__global__ void vq_norms(const float* __restrict__ cb) {
    int w = (blockIdx.x * blockDim.x + threadIdx.x) >> 5;
    int lane = threadIdx.x & 31;
    if (w < KCODES) {
        float v0 = cb[w * DDIM + lane];
        float v1 = cb[w * DDIM + 32 + lane];
        float s = v0 * v0 + v1 * v1;
        #pragma unroll
        for (int m = 16; m >= 1; m >>= 1) s += __shfl_xor_sync(0xffffffffu, s, m);
        if (lane == 0) g_hn[w] = 0.5f * s;
    }
}

__device__ __forceinline__ uint32_t f2tf32(float v) {
    uint32_t r; asm("cvt.rna.tf32.f32 %0, %1;" : "=r"(r) : "f"(v)); return r;
}

// One-shot: split codebook to tf32 hi/lo in mma fragment order (+ folded-norm kstep).
__global__ void vq_bfrag(const float* __restrict__ cb) {
    int idx = blockIdx.x * 256 + threadIdx.x;
    if (idx < NCH * TN * DDIM) {
        int ch = idx >> 13, rem = idx & 8191;
        int n = rem >> 6, k = rem & 63;
        float v = cb[(ch * TN + n) * DDIM + k];
        uint32_t hi = f2tf32(v);
        uint32_t lo = f2tf32(v - __uint_as_float(hi));
        int slot = ((((k >> 3) * 16 + (n >> 3)) * 32) + ((n & 7) * 4 + (k & 3))) * 2
                 + ((k >> 2) & 1);
        g_bhi[ch * BHI_U32 + slot] = hi;
        g_blo[ch * BLO_U32 + slot] = lo;
    } else {
        int e = idx - NCH * TN * DDIM;           // norm kstep entries
        if (e < NCH * 1024) {
            int ch = e >> 10, ee = e & 1023;
            int j = ee >> 6, ln = (ee >> 1) & 31, half = ee & 1;
            int tg = ln & 3, n = (j << 3) | (ln >> 2);
            uint32_t val = 0;
            if (half == 0 && tg < 2) {
                float hn = -g_hn[ch * TN + n];
                uint32_t hh = f2tf32(hn);
                val = (tg == 0) ? hh : f2tf32(hn - __uint_as_float(hh));
            }
            g_bhi[ch * BHI_U32 + (((8 * 16 + j) * 32) + ln) * 2 + half] = val;
        }
    }
}

#define MMA(d, a0, a1, a2, a3, b0, b1)                                        \
    asm("mma.sync.aligned.m16n8k8.row.col.f32.tf32.tf32.f32 "                 \
        "{%0,%1,%2,%3}, {%4,%5,%6,%7}, {%8,%9}, {%0,%1,%2,%3};"               \
        : "+f"((d)[0]), "+f"((d)[1]), "+f"((d)[2]), "+f"((d)[3])              \
        : "r"(a0), "r"(a1), "r"(a2), "r"(a3), "r"(b0), "r"(b1))

// Main: pure LDG(L2-hot fragments) + MMA chunk loop; no syncthreads inside.
__global__ __launch_bounds__(256, 1)
void vq_tc(const float* __restrict__ inp, const float* __restrict__ cb,
           float* __restrict__ out, int out_size) {
    extern __shared__ char smem[];
    int*   sidx = (int*)(smem + SM_IDX);
    float* araw = (float*)(smem + SM_A);        // [128][65], A staging only

    int tid = threadIdx.x, wid = tid >> 5, lane = tid & 31;
    int gid = lane >> 2, tig = lane & 3;
    int n0 = blockIdx.x * TM;
    int b = n0 >> 12, s0 = n0 & (HW - 1);
    const float* ibase = inp + (long long)b * DDIM * HW + s0;

    for (int e = tid; e < TM * DDIM; e += 256) {
        int t = e & 127, d = e >> 7;
        araw[t * 65 + d] = ibase[d * HW + t];
    }
    __syncthreads();

    int r0 = wid * 16 + gid, r1 = r0 + 8;
    uint32_t ahi[8][4], alo[8][4];
    #pragma unroll
    for (int s = 0; s < 8; ++s) {
        float v[4] = { araw[r0 * 65 + s * 8 + tig],     araw[r1 * 65 + s * 8 + tig],
                       araw[r0 * 65 + s * 8 + tig + 4], araw[r1 * 65 + s * 8 + tig + 4] };
        #pragma unroll
        for (int i = 0; i < 4; ++i) {
            ahi[s][i] = f2tf32(v[i]);
            alo[s][i] = f2tf32(v[i] - __uint_as_float(ahi[s][i]));
        }
    }
    uint32_t an = (tig < 2) ? 0x3f800000u : 0u;   // A cols 64,65 = 1.0

    float best0 = -3.4e38f, best1 = -3.4e38f;
    int bi0 = 0, bi1 = 0;

    for (int ch = 0; ch < NCH; ++ch) {
        int c0 = ch * TN;
        const uint2* gbh = (const uint2*)(g_bhi + ch * BHI_U32) + lane;
        const uint2* gbl = (const uint2*)(g_blo + ch * BLO_U32) + lane;

        float acc[16][4];
        #pragma unroll
        for (int j = 0; j < 16; ++j)
            #pragma unroll
            for (int i = 0; i < 4; ++i) acc[j][i] = 0.f;

        #pragma unroll
        for (int s = 0; s < 8; ++s)
            #pragma unroll
            for (int j = 0; j < 16; ++j) {
                uint2 bh = gbh[(s * 16 + j) * 32];
                uint2 bl = gbl[(s * 16 + j) * 32];
                MMA(acc[j], ahi[s][0], ahi[s][1], ahi[s][2], ahi[s][3], bh.x, bh.y);
                MMA(acc[j], ahi[s][0], ahi[s][1], ahi[s][2], ahi[s][3], bl.x, bl.y);
                MMA(acc[j], alo[s][0], alo[s][1], alo[s][2], alo[s][3], bh.x, bh.y);
            }
        #pragma unroll
        for (int j = 0; j < 16; ++j) {
            uint2 bn = gbh[(8 * 16 + j) * 32];
            MMA(acc[j], an, an, 0u, 0u, bn.x, bn.y);
        }

        // Running argmax (cols ascend with j and within pairs -> strict > = lowest idx)
        #pragma unroll
        for (int j = 0; j < 16; ++j) {
            int colb = c0 + j * 8 + tig * 2;
            if (acc[j][0] > best0) { best0 = acc[j][0]; bi0 = colb; }
            if (acc[j][1] > best0) { best0 = acc[j][1]; bi0 = colb + 1; }
            if (acc[j][2] > best1) { best1 = acc[j][2]; bi1 = colb; }
            if (acc[j][3] > best1) { best1 = acc[j][3]; bi1 = colb + 1; }
        }
    }

    // Quad reduce (lanes differing in tig hold different columns)
    #pragma unroll
    for (int m = 1; m <= 2; m <<= 1) {
        float ov; int oi;
        ov = __shfl_xor_sync(0xffffffffu, best0, m);
        oi = __shfl_xor_sync(0xffffffffu, bi0, m);
        if (ov > best0 || (ov == best0 && oi < bi0)) { best0 = ov; bi0 = oi; }
        ov = __shfl_xor_sync(0xffffffffu, best1, m);
        oi = __shfl_xor_sync(0xffffffffu, bi1, m);
        if (ov > best1 || (ov == best1 && oi < bi1)) { best1 = ov; bi1 = oi; }
    }
    if (tig == 0) { sidx[r0] = bi0; sidx[r1] = bi1; }
    __syncthreads();

    // Fused gather: out[b][d][s0+t] = cb[idx[t]][d]; coalesced writes, L2-hot reads.
    for (int e = tid; e < TM * DDIM; e += 256) {
        int d = e >> 7, t = e & 127;
        out[((long long)b * DDIM + d) * HW + s0 + t] = cb[sidx[t] * DDIM + d];
    }
    if (out_size > TOKENS * DDIM && tid < TM)
        out[TOKENS * DDIM + n0 + tid] = (float)sidx[tid];
}

extern "C" void kernel_launch(void* const* d_in, const int* in_sizes, int n_in,
                              void* d_out, int out_size) {
    const float* inp = (const float*)d_in[0];   // (16, 64, 64, 64) f32
    const float* cb  = (const float*)d_in[1];   // (1024, 64) f32
    float* out = (float*)d_out;

    cudaFuncSetAttribute(vq_tc, cudaFuncAttributeMaxDynamicSharedMemorySize, SMEM_TOTAL);

    vq_norms<<<KCODES * 32 / 256, 256>>>(cb);
    vq_bfrag<<<(NCH * TN * DDIM + NCH * 1024 + 255) / 256, 256>>>(cb);
    vq_tc<<<TOKENS / TM, 256, SMEM_TOTAL>>>(inp, cb, out, out_size);
}

// round 12
// speedup vs baseline: 1.4878x; 1.0249x over previous
#include <cuda_runtime.h>
#include <cstdint>

#define TOKENS 65536
#define KCODES 1024
#define DDIM   64
#define HW     4096
#define TM     128
#define TN     128
#define NCH    (KCODES / TN)

#define BHI_U32 (9 * 16 * 64)     // per chunk: 9 ksteps (8 data + 1 folded-norm)
#define BLO_U32 (8 * 16 * 64)
#define CHUNK_BYTES ((BHI_U32 + BLO_U32) * 4)   // 69632

#define SM_IDX 0
#define SM_BUF 512
#define SMEM_TOTAL (SM_BUF + 2 * CHUNK_BYTES)    // 139776 B

__device__ float    g_hn[KCODES];
__device__ uint32_t g_bhi[NCH * BHI_U32];   // fragment-ordered, precomputed once
__device__ uint32_t g_blo[NCH * BLO_U32];

__global__ void vq_norms(const float* __restrict__ cb) {
    int w = (blockIdx.x * blockDim.x + threadIdx.x) >> 5;
    int lane = threadIdx.x & 31;
    if (w < KCODES) {
        float v0 = cb[w * DDIM + lane];
        float v1 = cb[w * DDIM + 32 + lane];
        float s = v0 * v0 + v1 * v1;
        #pragma unroll
        for (int m = 16; m >= 1; m >>= 1) s += __shfl_xor_sync(0xffffffffu, s, m);
        if (lane == 0) g_hn[w] = 0.5f * s;
    }
}

__device__ __forceinline__ uint32_t f2tf32(float v) {
    uint32_t r; asm("cvt.rna.tf32.f32 %0, %1;" : "=r"(r) : "f"(v)); return r;
}

// One-shot: split codebook to tf32 hi/lo in mma fragment order (+ folded-norm kstep).
__global__ void vq_bfrag(const float* __restrict__ cb) {
    int idx = blockIdx.x * 256 + threadIdx.x;
    if (idx < NCH * TN * DDIM) {
        int ch = idx >> 13, rem = idx & 8191;
        int n = rem >> 6, k = rem & 63;
        float v = cb[(ch * TN + n) * DDIM + k];
        uint32_t hi = f2tf32(v);
        uint32_t lo = f2tf32(v - __uint_as_float(hi));
        int slot = ((((k >> 3) * 16 + (n >> 3)) * 32) + ((n & 7) * 4 + (k & 3))) * 2
                 + ((k >> 2) & 1);
        g_bhi[ch * BHI_U32 + slot] = hi;
        g_blo[ch * BLO_U32 + slot] = lo;
    } else {
        int e = idx - NCH * TN * DDIM;           // norm kstep entries
        if (e < NCH * 1024) {
            int ch = e >> 10, ee = e & 1023;
            int j = ee >> 6, ln = (ee >> 1) & 31, half = ee & 1;
            int tg = ln & 3, n = (j << 3) | (ln >> 2);
            uint32_t val = 0;
            if (half == 0 && tg < 2) {
                float hn = -g_hn[ch * TN + n];
                uint32_t hh = f2tf32(hn);
                val = (tg == 0) ? hh : f2tf32(hn - __uint_as_float(hh));
            }
            g_bhi[ch * BHI_U32 + (((8 * 16 + j) * 32) + ln) * 2 + half] = val;
        }
    }
}

#define MMA(d, a0, a1, a2, a3, b0, b1)                                        \
    asm("mma.sync.aligned.m16n8k8.row.col.f32.tf32.tf32.f32 "                 \
        "{%0,%1,%2,%3}, {%4,%5,%6,%7}, {%8,%9}, {%0,%1,%2,%3};"               \
        : "+f"((d)[0]), "+f"((d)[1]), "+f"((d)[2]), "+f"((d)[3])              \
        : "r"(a0), "r"(a1), "r"(a2), "r"(a3), "r"(b0), "r"(b1))

#define CP16(dst, src) \
    asm volatile("cp.async.cg.shared.global [%0], [%1], 16;" \
                 :: "r"(dst), "l"(src) : "memory")

// Main: double-buffered cp.async staging of B fragments; MMA from smem LDS.64.
__global__ __launch_bounds__(256, 1)
void vq_tc(const float* __restrict__ inp, const float* __restrict__ cb,
           float* __restrict__ out, int out_size) {
    extern __shared__ char smem[];
    int*   sidx = (int*)(smem + SM_IDX);
    float* araw = (float*)(smem + SM_BUF);      // [128][65] A staging (dies before ch0)
    uint32_t sbase = (uint32_t)__cvta_generic_to_shared(smem);

    int tid = threadIdx.x, wid = tid >> 5, lane = tid & 31;
    int gid = lane >> 2, tig = lane & 3;
    int n0 = blockIdx.x * TM;
    int b = n0 >> 12, s0 = n0 & (HW - 1);
    const float* ibase = inp + (long long)b * DDIM * HW + s0;

    for (int e = tid; e < TM * DDIM; e += 256) {
        int t = e & 127, d = e >> 7;
        araw[t * 65 + d] = ibase[d * HW + t];
    }
    __syncthreads();

    int r0 = wid * 16 + gid, r1 = r0 + 8;
    uint32_t ahi[8][4], alo[8][4];
    #pragma unroll
    for (int s = 0; s < 8; ++s) {
        float v[4] = { araw[r0 * 65 + s * 8 + tig],     araw[r1 * 65 + s * 8 + tig],
                       araw[r0 * 65 + s * 8 + tig + 4], araw[r1 * 65 + s * 8 + tig + 4] };
        #pragma unroll
        for (int i = 0; i < 4; ++i) {
            ahi[s][i] = f2tf32(v[i]);
            alo[s][i] = f2tf32(v[i] - __uint_as_float(ahi[s][i]));
        }
    }
    uint32_t an = (tig < 2) ? 0x3f800000u : 0u;   // A cols 64,65 = 1.0
    __syncthreads();                               // araw dead; buffers may be written

    // Prefetch chunk 0 into buffer 0
    {
        uint32_t dst = sbase + SM_BUF;
        const char* shi = (const char*)g_bhi;
        const char* slo = (const char*)g_blo;
        #pragma unroll
        for (int i = 0; i < 9; ++i)
            CP16(dst + (tid + i * 256) * 16, shi + (tid + i * 256) * 16);
        #pragma unroll
        for (int i = 0; i < 8; ++i)
            CP16(dst + BHI_U32 * 4 + (tid + i * 256) * 16, slo + (tid + i * 256) * 16);
        asm volatile("cp.async.commit_group;" ::: "memory");
    }

    float best0 = -3.4e38f, best1 = -3.4e38f;
    int bi0 = 0, bi1 = 0;

    for (int ch = 0; ch < NCH; ++ch) {
        // Prefetch next chunk into the other buffer
        if (ch + 1 < NCH) {
            uint32_t dst = sbase + SM_BUF + ((ch + 1) & 1) * CHUNK_BYTES;
            const char* shi = (const char*)(g_bhi + (ch + 1) * BHI_U32);
            const char* slo = (const char*)(g_blo + (ch + 1) * BLO_U32);
            #pragma unroll
            for (int i = 0; i < 9; ++i)
                CP16(dst + (tid + i * 256) * 16, shi + (tid + i * 256) * 16);
            #pragma unroll
            for (int i = 0; i < 8; ++i)
                CP16(dst + BHI_U32 * 4 + (tid + i * 256) * 16, slo + (tid + i * 256) * 16);
            asm volatile("cp.async.commit_group;" ::: "memory");
            asm volatile("cp.async.wait_group 1;" ::: "memory");
        } else {
            asm volatile("cp.async.wait_group 0;" ::: "memory");
        }
        __syncthreads();   // current buffer fully staged, previous buffer free

        const char* buf = smem + SM_BUF + (ch & 1) * CHUNK_BYTES;
        const uint2* sbh = (const uint2*)buf + lane;
        const uint2* sbl = (const uint2*)(buf + BHI_U32 * 4) + lane;
        int c0 = ch * TN;

        float acc[16][4];
        #pragma unroll
        for (int j = 0; j < 16; ++j)
            #pragma unroll
            for (int i = 0; i < 4; ++i) acc[j][i] = 0.f;

        #pragma unroll
        for (int s = 0; s < 8; ++s)
            #pragma unroll
            for (int j = 0; j < 16; ++j) {
                uint2 bh = sbh[(s * 16 + j) * 32];
                uint2 bl = sbl[(s * 16 + j) * 32];
                MMA(acc[j], ahi[s][0], ahi[s][1], ahi[s][2], ahi[s][3], bh.x, bh.y);
                MMA(acc[j], ahi[s][0], ahi[s][1], ahi[s][2], ahi[s][3], bl.x, bl.y);
                MMA(acc[j], alo[s][0], alo[s][1], alo[s][2], alo[s][3], bh.x, bh.y);
            }
        #pragma unroll
        for (int j = 0; j < 16; ++j) {
            uint2 bn = sbh[(8 * 16 + j) * 32];
            MMA(acc[j], an, an, 0u, 0u, bn.x, bn.y);
        }

        // Running argmax (cols ascend with j and within pairs -> strict > = lowest idx)
        #pragma unroll
        for (int j = 0; j < 16; ++j) {
            int colb = c0 + j * 8 + tig * 2;
            if (acc[j][0] > best0) { best0 = acc[j][0]; bi0 = colb; }
            if (acc[j][1] > best0) { best0 = acc[j][1]; bi0 = colb + 1; }
            if (acc[j][2] > best1) { best1 = acc[j][2]; bi1 = colb; }
            if (acc[j][3] > best1) { best1 = acc[j][3]; bi1 = colb + 1; }
        }
        __syncthreads();   // all warps done reading buf before it is re-staged
    }

    // Quad reduce (lanes differing in tig hold different columns)
    #pragma unroll
    for (int m = 1; m <= 2; m <<= 1) {
        float ov; int oi;
        ov = __shfl_xor_sync(0xffffffffu, best0, m);
        oi = __shfl_xor_sync(0xffffffffu, bi0, m);
        if (ov > best0 || (ov == best0 && oi < bi0)) { best0 = ov; bi0 = oi; }
        ov = __shfl_xor_sync(0xffffffffu, best1, m);
        oi = __shfl_xor_sync(0xffffffffu, bi1, m);
        if (ov > best1 || (ov == best1 && oi < bi1)) { best1 = ov; bi1 = oi; }
    }
    if (tig == 0) { sidx[r0] = bi0; sidx[r1] = bi1; }
    __syncthreads();

    // Fused gather: out[b][d][s0+t] = cb[idx[t]][d]; coalesced writes, L2-hot reads.
    for (int e = tid; e < TM * DDIM; e += 256) {
        int d = e >> 7, t = e & 127;
        out[((long long)b * DDIM + d) * HW + s0 + t] = cb[sidx[t] * DDIM + d];
    }
    if (out_size > TOKENS * DDIM && tid < TM)
        out[TOKENS * DDIM + n0 + tid] = (float)sidx[tid];
}

extern "C" void kernel_launch(void* const* d_in, const int* in_sizes, int n_in,
                              void* d_out, int out_size) {
    const float* inp = (const float*)d_in[0];   // (16, 64, 64, 64) f32
    const float* cb  = (const float*)d_in[1];   // (1024, 64) f32
    float* out = (float*)d_out;

    cudaFuncSetAttribute(vq_tc, cudaFuncAttributeMaxDynamicSharedMemorySize, SMEM_TOTAL);

    vq_norms<<<KCODES * 32 / 256, 256>>>(cb);
    vq_bfrag<<<(NCH * TN * DDIM + NCH * 1024 + 255) / 256, 256>>>(cb);
    vq_tc<<<TOKENS / TM, 256, SMEM_TOTAL>>>(inp, cb, out, out_size);
}

// round 14
// speedup vs baseline: 1.5488x; 1.0409x over previous
#include <cuda_runtime.h>
#include <cstdint>

#define TOKENS 65536
#define KCODES 1024
#define DDIM   64
#define HW     4096
#define TM     128
#define TN     128
#define NCH    (KCODES / TN)

#define BHI_U32 (9 * 16 * 64)     // per chunk: 9 ksteps (8 data + 1 folded-norm)
#define BLO_U32 (8 * 16 * 64)
#define CHUNK_BYTES ((BHI_U32 + BLO_U32) * 4)   // 69632

#define SM_IDX 0
#define SM_ALO 512                               // 8 warps x 8 s x 32 lanes x 16B = 32 KB
#define SM_BUF (SM_ALO + 32768)
#define SMEM_TOTAL (SM_BUF + CHUNK_BYTES)        // 102912 B -> 2 CTAs/SM

__device__ float    g_hn[KCODES];
__device__ uint32_t g_bhi[NCH * BHI_U32];   // fragment-ordered, precomputed once
__device__ uint32_t g_blo[NCH * BLO_U32];

__global__ void vq_norms(const float* __restrict__ cb) {
    int w = (blockIdx.x * blockDim.x + threadIdx.x) >> 5;
    int lane = threadIdx.x & 31;
    if (w < KCODES) {
        float v0 = cb[w * DDIM + lane];
        float v1 = cb[w * DDIM + 32 + lane];
        float s = v0 * v0 + v1 * v1;
        #pragma unroll
        for (int m = 16; m >= 1; m >>= 1) s += __shfl_xor_sync(0xffffffffu, s, m);
        if (lane == 0) g_hn[w] = 0.5f * s;
    }
}

__device__ __forceinline__ uint32_t f2tf32(float v) {
    uint32_t r; asm("cvt.rna.tf32.f32 %0, %1;" : "=r"(r) : "f"(v)); return r;
}

// One-shot: split codebook to tf32 hi/lo in mma fragment order (+ folded-norm kstep).
__global__ void vq_bfrag(const float* __restrict__ cb) {
    int idx = blockIdx.x * 256 + threadIdx.x;
    if (idx < NCH * TN * DDIM) {
        int ch = idx >> 13, rem = idx & 8191;
        int n = rem >> 6, k = rem & 63;
        float v = cb[(ch * TN + n) * DDIM + k];
        uint32_t hi = f2tf32(v);
        uint32_t lo = f2tf32(v - __uint_as_float(hi));
        int slot = ((((k >> 3) * 16 + (n >> 3)) * 32) + ((n & 7) * 4 + (k & 3))) * 2
                 + ((k >> 2) & 1);
        g_bhi[ch * BHI_U32 + slot] = hi;
        g_blo[ch * BLO_U32 + slot] = lo;
    } else {
        int e = idx - NCH * TN * DDIM;           // norm kstep entries
        if (e < NCH * 1024) {
            int ch = e >> 10, ee = e & 1023;
            int j = ee >> 6, ln = (ee >> 1) & 31, half = ee & 1;
            int tg = ln & 3, n = (j << 3) | (ln >> 2);
            uint32_t val = 0;
            if (half == 0 && tg < 2) {
                float hn = -g_hn[ch * TN + n];
                uint32_t hh = f2tf32(hn);
                val = (tg == 0) ? hh : f2tf32(hn - __uint_as_float(hh));
            }
            g_bhi[ch * BHI_U32 + (((8 * 16 + j) * 32) + ln) * 2 + half] = val;
        }
    }
}

#define MMA(d, a0, a1, a2, a3, b0, b1)                                        \
    asm("mma.sync.aligned.m16n8k8.row.col.f32.tf32.tf32.f32 "                 \
        "{%0,%1,%2,%3}, {%4,%5,%6,%7}, {%8,%9}, {%0,%1,%2,%3};"               \
        : "+f"((d)[0]), "+f"((d)[1]), "+f"((d)[2]), "+f"((d)[3])              \
        : "r"(a0), "r"(a1), "r"(a2), "r"(a3), "r"(b0), "r"(b1))

#define CP16(dst, src) \
    asm volatile("cp.async.cg.shared.global [%0], [%1], 16;" \
                 :: "r"(dst), "l"(src) : "memory")

// Main: 2 CTAs/SM; single staged buffer (cross-CTA overlap hides sync bubbles);
// A-hi fragments in regs, A-lo fragments in smem (LDS.128 per kstep).
__global__ __launch_bounds__(256, 2)
void vq_tc(const float* __restrict__ inp, const float* __restrict__ cb,
           float* __restrict__ out, int out_size) {
    extern __shared__ char smem[];
    int*   sidx = (int*)(smem + SM_IDX);
    float* araw = (float*)(smem + SM_BUF);      // [128][65] transient A staging
    uint32_t sbase = (uint32_t)__cvta_generic_to_shared(smem);

    int tid = threadIdx.x, wid = tid >> 5, lane = tid & 31;
    int gid = lane >> 2, tig = lane & 3;
    int n0 = blockIdx.x * TM;
    int b = n0 >> 12, s0 = n0 & (HW - 1);
    const float* ibase = inp + (long long)b * DDIM * HW + s0;

    for (int e = tid; e < TM * DDIM; e += 256) {
        int t = e & 127, d = e >> 7;
        araw[t * 65 + d] = ibase[d * HW + t];
    }
    __syncthreads();

    int r0 = wid * 16 + gid, r1 = r0 + 8;
    uint32_t ahi[8][4];
    // Build ahi (regs) and alo (smem, per-warp fragment-ordered [s][lane][0..3])
    #pragma unroll
    for (int s = 0; s < 8; ++s) {
        float v[4] = { araw[r0 * 65 + s * 8 + tig],     araw[r1 * 65 + s * 8 + tig],
                       araw[r0 * 65 + s * 8 + tig + 4], araw[r1 * 65 + s * 8 + tig + 4] };
        uint32_t lo[4];
        #pragma unroll
        for (int i = 0; i < 4; ++i) {
            ahi[s][i] = f2tf32(v[i]);
            lo[i] = f2tf32(v[i] - __uint_as_float(ahi[s][i]));
        }
        uint32_t dst = sbase + SM_ALO + wid * 4096 + (s * 32 + lane) * 16;
        asm volatile("st.shared.v4.b32 [%0], {%1,%2,%3,%4};"
                     :: "r"(dst), "r"(lo[0]), "r"(lo[1]), "r"(lo[2]), "r"(lo[3])
                     : "memory");
    }
    uint32_t an = (tig < 2) ? 0x3f800000u : 0u;   // A cols 64,65 = 1.0
    __syncthreads();                               // araw dead; buffer reusable

    float best0 = -3.4e38f, best1 = -3.4e38f;
    int bi0 = 0, bi1 = 0;
    uint32_t alo_base = sbase + SM_ALO + wid * 4096 + lane * 16;

    for (int ch = 0; ch < NCH; ++ch) {
        // Stage this chunk's fragments (17 x 16B per thread)
        {
            uint32_t dst = sbase + SM_BUF;
            const char* shi = (const char*)(g_bhi + ch * BHI_U32);
            const char* slo = (const char*)(g_blo + ch * BLO_U32);
            #pragma unroll
            for (int i = 0; i < 9; ++i)
                CP16(dst + (tid + i * 256) * 16, shi + (tid + i * 256) * 16);
            #pragma unroll
            for (int i = 0; i < 8; ++i)
                CP16(dst + BHI_U32 * 4 + (tid + i * 256) * 16, slo + (tid + i * 256) * 16);
            asm volatile("cp.async.commit_group;" ::: "memory");
            asm volatile("cp.async.wait_group 0;" ::: "memory");
        }
        __syncthreads();   // buffer staged for all warps

        const char* buf = smem + SM_BUF;
        const uint2* sbh = (const uint2*)buf + lane;
        const uint2* sbl = (const uint2*)(buf + BHI_U32 * 4) + lane;
        int c0 = ch * TN;

        float acc[16][4];
        #pragma unroll
        for (int j = 0; j < 16; ++j)
            #pragma unroll
            for (int i = 0; i < 4; ++i) acc[j][i] = 0.f;

        #pragma unroll
        for (int s = 0; s < 8; ++s) {
            uint32_t al[4];
            asm volatile("ld.shared.v4.b32 {%0,%1,%2,%3}, [%4];"
                         : "=r"(al[0]), "=r"(al[1]), "=r"(al[2]), "=r"(al[3])
                         : "r"(alo_base + s * 512));
            #pragma unroll
            for (int j = 0; j < 16; ++j) {
                uint2 bh = sbh[(s * 16 + j) * 32];
                uint2 bl = sbl[(s * 16 + j) * 32];
                MMA(acc[j], ahi[s][0], ahi[s][1], ahi[s][2], ahi[s][3], bh.x, bh.y);
                MMA(acc[j], ahi[s][0], ahi[s][1], ahi[s][2], ahi[s][3], bl.x, bl.y);
                MMA(acc[j], al[0], al[1], al[2], al[3], bh.x, bh.y);
            }
        }
        #pragma unroll
        for (int j = 0; j < 16; ++j) {
            uint2 bn = sbh[(8 * 16 + j) * 32];
            MMA(acc[j], an, an, 0u, 0u, bn.x, bn.y);
        }

        // Running argmax (cols ascend with j and within pairs -> strict > = lowest idx)
        #pragma unroll
        for (int j = 0; j < 16; ++j) {
            int colb = c0 + j * 8 + tig * 2;
            if (acc[j][0] > best0) { best0 = acc[j][0]; bi0 = colb; }
            if (acc[j][1] > best0) { best0 = acc[j][1]; bi0 = colb + 1; }
            if (acc[j][2] > best1) { best1 = acc[j][2]; bi1 = colb; }
            if (acc[j][3] > best1) { best1 = acc[j][3]; bi1 = colb + 1; }
        }
        __syncthreads();   // all warps done reading buf before next restage
    }

    // Quad reduce (lanes differing in tig hold different columns)
    #pragma unroll
    for (int m = 1; m <= 2; m <<= 1) {
        float ov; int oi;
        ov = __shfl_xor_sync(0xffffffffu, best0, m);
        oi = __shfl_xor_sync(0xffffffffu, bi0, m);
        if (ov > best0 || (ov == best0 && oi < bi0)) { best0 = ov; bi0 = oi; }
        ov = __shfl_xor_sync(0xffffffffu, best1, m);
        oi = __shfl_xor_sync(0xffffffffu, bi1, m);
        if (ov > best1 || (ov == best1 && oi < bi1)) { best1 = ov; bi1 = oi; }
    }
    if (tig == 0) { sidx[r0] = bi0; sidx[r1] = bi1; }
    __syncthreads();

    // Fused gather: out[b][d][s0+t] = cb[idx[t]][d]; coalesced writes, L2-hot reads.
    for (int e = tid; e < TM * DDIM; e += 256) {
        int d = e >> 7, t = e & 127;
        out[((long long)b * DDIM + d) * HW + s0 + t] = cb[sidx[t] * DDIM + d];
    }
    if (out_size > TOKENS * DDIM && tid < TM)
        out[TOKENS * DDIM + n0 + tid] = (float)sidx[tid];
}

extern "C" void kernel_launch(void* const* d_in, const int* in_sizes, int n_in,
                              void* d_out, int out_size) {
    const float* inp = (const float*)d_in[0];   // (16, 64, 64, 64) f32
    const float* cb  = (const float*)d_in[1];   // (1024, 64) f32
    float* out = (float*)d_out;

    cudaFuncSetAttribute(vq_tc, cudaFuncAttributeMaxDynamicSharedMemorySize, SMEM_TOTAL);

    vq_norms<<<KCODES * 32 / 256, 256>>>(cb);
    vq_bfrag<<<(NCH * TN * DDIM + NCH * 1024 + 255) / 256, 256>>>(cb);
    vq_tc<<<TOKENS / TM, 256, SMEM_TOTAL>>>(inp, cb, out, out_size);
}